// round 1
// baseline (speedup 1.0000x reference)
#include <cuda_runtime.h>
#include <cuda_bf16.h>
#include <math.h>
#include <stdint.h>

// Problem constants
#define BB 16
#define CC 8
#define LL 16384
#define WW 256
#define RR 32

// Precomputed Gabor bank: [filter(256)][tap(256)] as (real, imag)
__device__ float2 g_bank[WW * CC * RR / WW * WW]; // 256*256 float2 = 512 KB
// (written as 256*256 below; the expression above equals 65536)

__global__ void bank_kernel(const float* __restrict__ kV, const float* __restrict__ sV) {
    int idx = blockIdx.x * blockDim.x + threadIdx.x; // 0..65535
    if (idx >= 256 * 256) return;
    int f = idx >> 8;      // filter index 0..255
    int w = idx & 255;     // tap
    float k = kV[f];
    float s = sV[f];
    // Replicate reference f32 arithmetic for the phase, then exact cos/sin of it.
    float c0 = (float)(-2.0 * M_PI / 256.0);
    float a = c0 * k;
    float phase = a * (float)w;
    double sp, cp;
    sincos((double)phase, &sp, &cp);
    float nm = (float)w - 128.0f;
    float s2 = s * s;
    float inv2s2 = 1.0f / (2.0f * s2);
    float coef = 1.0f / sqrtf(2.0f * (float)M_PI * s2);
    float gauss = coef * expf(-inv2s2 * nm * nm);
    g_bank[idx] = make_float2((float)cp * gauss, (float)sp * gauss);
}

__device__ __forceinline__ unsigned long long ffma2(unsigned long long a,
                                                    unsigned long long b,
                                                    unsigned long long c) {
    unsigned long long d;
    asm("fma.rn.f32x2 %0, %1, %2, %3;" : "=l"(d) : "l"(a), "l"(b), "l"(c));
    return d;
}

#define TT 256        // t-positions per block
#define NTHREADS 512  // 16 warps; each warp = one group of 16 consecutive t, lane = r
#define FSTRIDE 33    // float2 row stride for filter smem (pad to avoid conflicts)

// Dynamic smem layout:
//   float2 filt[256 * 33]              (67584 B)  filt[w*33 + r] = (fr, fi), r already output-order
//   float2 xd[520]                     (4160 B)   duplicated (v,v), covers t0-128 .. t0+TT+127 (+pad)
#define FILT_BYTES (WW * FSTRIDE * 8)
#define XD_ELEMS 520
#define SMEM_BYTES (FILT_BYTES + XD_ELEMS * 8)

__global__ void __launch_bounds__(NTHREADS, 1)
conv_kernel(const float* __restrict__ x, float* __restrict__ out) {
    extern __shared__ unsigned char smem_raw[];
    float2* filt = reinterpret_cast<float2*>(smem_raw);
    float2* xd   = reinterpret_cast<float2*>(smem_raw + FILT_BYTES);

    int bid  = blockIdx.x;
    int tile = bid & 63;          // 64 tiles of 256
    int c    = (bid >> 6) & 7;
    int b    = bid >> 9;
    int t0   = tile * TT;

    // ---- Stage filters for channel c, output-r order (R reversed) ----
    // filt[w][r] <- g_bank[c*32 + (31 - r)][w]
    for (int idx = threadIdx.x; idx < RR * WW; idx += NTHREADS) {
        int r = idx >> 8;
        int w = idx & 255;
        int fidx = c * RR + (RR - 1 - r);
        filt[w * FSTRIDE + r] = g_bank[fidx * WW + w];
    }

    // ---- Stage x tile, duplicated (v, v) ----
    const float* xb = x + (size_t)b * LL * CC + c;
    for (int j = threadIdx.x; j < XD_ELEMS; j += NTHREADS) {
        int l = t0 - 128 + j;
        float v = (l >= 0 && l < LL) ? xb[(size_t)l * CC] : 0.0f;
        xd[j] = make_float2(v, v);
    }
    __syncthreads();

    int lane = threadIdx.x & 31;   // = output r
    int wid  = threadIdx.x >> 5;   // t-group: t = t0 + wid*16 + i

    // Packed (Re, Im) accumulators for 16 consecutive t
    unsigned long long acc[16];
#pragma unroll
    for (int i = 0; i < 16; i++) acc[i] = 0ULL;

    // Sliding register window over duplicated x, in packed-pair form.
    // Tap w for local t-index i reads xd[wid*16 + i + w].
    const ulonglong2* xp2 = reinterpret_cast<const ulonglong2*>(xd);
    const unsigned long long* fp =
        reinterpret_cast<const unsigned long long*>(filt) + lane;

    unsigned long long x0[16], x1[16];
    int mbase = wid * 8; // xd element (wid*16) / 2
#pragma unroll
    for (int q = 0; q < 8; q++) {
        ulonglong2 v = xp2[mbase + q];
        x0[2 * q] = v.x; x0[2 * q + 1] = v.y;
    }

    for (int w0 = 0; w0 < WW; w0 += 16) {
#pragma unroll
        for (int q = 0; q < 8; q++) {
            ulonglong2 v = xp2[mbase + 8 + (w0 >> 1) + q];
            x1[2 * q] = v.x; x1[2 * q + 1] = v.y;
        }
#pragma unroll
        for (int dw = 0; dw < 16; dw++) {
            unsigned long long f = fp[(w0 + dw) * FSTRIDE];
#pragma unroll
            for (int i = 0; i < 16; i++) {
                int j = dw + i; // 0..30, compile-time constant
                unsigned long long xv = (j < 16) ? x0[j] : x1[j - 16];
                acc[i] = ffma2(xv, f, acc[i]);
            }
        }
#pragma unroll
        for (int i = 0; i < 16; i++) x0[i] = x1[i];
    }

    // ---- Power + store: out[b][t][c*32 + r] ----
    int tbase = t0 + wid * 16;
    size_t obase = ((size_t)b * LL + tbase) * (CC * RR) + c * RR + lane;
#pragma unroll
    for (int i = 0; i < 16; i++) {
        float2 a = *reinterpret_cast<float2*>(&acc[i]);
        float p = a.x * a.x + a.y * a.y;
        out[obase + (size_t)i * (CC * RR)] = p;
    }
}

extern "C" void kernel_launch(void* const* d_in, const int* in_sizes, int n_in,
                              void* d_out, int out_size) {
    const float* x  = (const float*)d_in[0];
    const float* kV = (const float*)d_in[1];
    const float* sV = (const float*)d_in[2];
    float* out = (float*)d_out;

    // Allow >48KB dynamic smem (idempotent)
    cudaFuncSetAttribute(conv_kernel, cudaFuncAttributeMaxDynamicSharedMemorySize,
                         SMEM_BYTES);

    // 1) Build Gabor bank (256 filters x 256 taps)
    bank_kernel<<<256, 256>>>(kV, sV);

    // 2) Sliding Gabor power transform
    int nblocks = BB * CC * (LL / TT); // 8192
    conv_kernel<<<nblocks, NTHREADS, SMEM_BYTES>>>(x, out);
}

// round 2
// speedup vs baseline: 1.1803x; 1.1803x over previous
#include <cuda_runtime.h>
#include <cuda_bf16.h>
#include <math.h>
#include <stdint.h>

// Problem constants
#define BB 16
#define CC 8
#define LL 16384
#define WW 256
#define RR 32

// Precomputed Gabor bank: [filter(256)][tap(256)] as (real, imag)
__device__ float2 g_bank[256 * 256];          // 512 KB, L2-resident
__device__ unsigned int g_counter;            // persistent work queue head

__global__ void bank_kernel(const float* __restrict__ kV, const float* __restrict__ sV) {
    int idx = blockIdx.x * blockDim.x + threadIdx.x; // 0..65535
    if (idx == 0) g_counter = 0;  // reset work queue every launch (graph replays)
    if (idx >= 256 * 256) return;
    int f = idx >> 8;      // filter index 0..255
    int w = idx & 255;     // tap
    float k = kV[f];
    float s = sV[f];
    // Replicate reference f32 arithmetic for the phase, then exact cos/sin of it.
    float c0 = (float)(-2.0 * M_PI / 256.0);
    float a = c0 * k;
    float phase = a * (float)w;
    double sp, cp;
    sincos((double)phase, &sp, &cp);
    float nm = (float)w - 128.0f;
    float s2 = s * s;
    float inv2s2 = 1.0f / (2.0f * s2);
    float coef = 1.0f / sqrtf(2.0f * (float)M_PI * s2);
    float gauss = coef * expf(-inv2s2 * nm * nm);
    g_bank[idx] = make_float2((float)cp * gauss, (float)sp * gauss);
}

__device__ __forceinline__ unsigned long long ffma2(unsigned long long a,
                                                    unsigned long long b,
                                                    unsigned long long c) {
    unsigned long long d;
    asm("fma.rn.f32x2 %0, %1, %2, %3;" : "=l"(d) : "l"(a), "l"(b), "l"(c));
    return d;
}

#define TT 256        // t-positions per tile
#define NTHREADS 512  // 16 warps; each warp = 16 consecutive t, lane = r
#define FSTRIDE 33    // float2 row stride for filter smem (pad: conflict-free)
#define NTILES (BB * CC * (LL / TT))   // 8192, id layout: c-major (g>>10 = c)
#define NBLOCKS 160   // persistent blocks (>= SM count; extras drain instantly)

// Dynamic smem layout:
//   float2 filt[256 * 33]     (67584 B)  filt[w*33 + r] = (fr, fi), r output-order
//   float2 xd[2][520]         ( 8320 B)  double-buffered duplicated (v,v) x tiles
#define FILT_BYTES (WW * FSTRIDE * 8)
#define XD_ELEMS 520
#define SMEM_BYTES (FILT_BYTES + 2 * XD_ELEMS * 8)

__global__ void __launch_bounds__(NTHREADS, 1)
conv_kernel(const float* __restrict__ x, float* __restrict__ out) {
    extern __shared__ unsigned char smem_raw[];
    float2* filt = reinterpret_cast<float2*>(smem_raw);
    __shared__ unsigned int s_g[2];

    int tid  = threadIdx.x;
    int lane = tid & 31;   // = output r
    int wid  = tid >> 5;   // t-group: t = t0 + wid*16 + i

    // ---- initial grab ----
    if (tid == 0) s_g[0] = atomicAdd(&g_counter, 1u);
    __syncthreads();
    unsigned int g = s_g[0];

    // ---- prefetch x for first tile into registers ----
    float v0, v1;
    {
        unsigned int gc = (g < NTILES) ? g : 0u;
        int c = gc >> 10, b = (gc >> 6) & 15, t0 = (int)(gc & 63) << 8;
        const float* xb = x + (size_t)b * LL * CC + c;
        int l0 = t0 - 128 + tid;
        v0 = (l0 >= 0 && l0 < LL) ? xb[(size_t)l0 * CC] : 0.0f;
        v1 = 0.0f;
        if (tid < XD_ELEMS - NTHREADS) {
            int l1 = l0 + NTHREADS;
            v1 = (l1 >= 0 && l1 < LL) ? xb[(size_t)l1 * CC] : 0.0f;
        }
    }

    int cur_c = -1;
    int buf = 0;
    while (g < NTILES) {
        int c  = g >> 10;
        int b  = (g >> 6) & 15;
        int t0 = (int)(g & 63) << 8;
        float2* xd = reinterpret_cast<float2*>(smem_raw + FILT_BYTES) + buf * XD_ELEMS;

        // stage prefetched x into this iteration's buffer (duplicated (v,v))
        xd[tid] = make_float2(v0, v0);
        if (tid < XD_ELEMS - NTHREADS) xd[tid + NTHREADS] = make_float2(v1, v1);

        // grab next tile (published after barrier via alternate slot)
        if (tid == 0) s_g[buf ^ 1] = atomicAdd(&g_counter, 1u);

        // (re)stage filters only on channel change — rare with in-order grabs
        if (c != cur_c) {
            __syncthreads();  // protect readers of old filt
            for (int idx = tid; idx < RR * WW; idx += NTHREADS) {
                int r = idx >> 8;
                int w = idx & 255;
                filt[w * FSTRIDE + r] = g_bank[(c * RR + (RR - 1 - r)) * WW + w];
            }
            cur_c = c;
        }
        __syncthreads();

        unsigned int gn = s_g[buf ^ 1];

        // prefetch x for next tile; LDG latency overlaps with the compute below
        {
            unsigned int gc = (gn < NTILES) ? gn : 0u;
            int cn = gc >> 10, bn = (gc >> 6) & 15, t0n = (int)(gc & 63) << 8;
            const float* xb = x + (size_t)bn * LL * CC + cn;
            int l0 = t0n - 128 + tid;
            v0 = (l0 >= 0 && l0 < LL) ? xb[(size_t)l0 * CC] : 0.0f;
            v1 = 0.0f;
            if (tid < XD_ELEMS - NTHREADS) {
                int l1 = l0 + NTHREADS;
                v1 = (l1 >= 0 && l1 < LL) ? xb[(size_t)l1 * CC] : 0.0f;
            }
        }

        // ---- compute: packed (Re,Im) accumulators for 16 consecutive t ----
        unsigned long long acc[16];
#pragma unroll
        for (int i = 0; i < 16; i++) acc[i] = 0ULL;

        const ulonglong2* xp2 = reinterpret_cast<const ulonglong2*>(xd);
        const unsigned long long* fp =
            reinterpret_cast<const unsigned long long*>(filt) + lane;

        unsigned long long x0[16], x1[16];
        int mbase = wid * 8; // xd element (wid*16) / 2
#pragma unroll
        for (int q = 0; q < 8; q++) {
            ulonglong2 v = xp2[mbase + q];
            x0[2 * q] = v.x; x0[2 * q + 1] = v.y;
        }

        for (int w0 = 0; w0 < WW; w0 += 16) {
#pragma unroll
            for (int q = 0; q < 8; q++) {
                ulonglong2 v = xp2[mbase + 8 + (w0 >> 1) + q];
                x1[2 * q] = v.x; x1[2 * q + 1] = v.y;
            }
#pragma unroll
            for (int dw = 0; dw < 16; dw++) {
                unsigned long long f = fp[(w0 + dw) * FSTRIDE];
#pragma unroll
                for (int i = 0; i < 16; i++) {
                    int j = dw + i; // compile-time constant 0..30
                    unsigned long long xv = (j < 16) ? x0[j] : x1[j - 16];
                    acc[i] = ffma2(xv, f, acc[i]);
                }
            }
#pragma unroll
            for (int i = 0; i < 16; i++) x0[i] = x1[i];
        }

        // ---- power + store: out[b][t][c*32 + r] ----
        int tbase = t0 + wid * 16;
        size_t obase = ((size_t)b * LL + tbase) * (CC * RR) + c * RR + lane;
#pragma unroll
        for (int i = 0; i < 16; i++) {
            float2 a = *reinterpret_cast<float2*>(&acc[i]);
            float p = a.x * a.x + a.y * a.y;
            out[obase + (size_t)i * (CC * RR)] = p;
        }

        g = gn;
        buf ^= 1;
    }
}

extern "C" void kernel_launch(void* const* d_in, const int* in_sizes, int n_in,
                              void* d_out, int out_size) {
    const float* x  = (const float*)d_in[0];
    const float* kV = (const float*)d_in[1];
    const float* sV = (const float*)d_in[2];
    float* out = (float*)d_out;

    cudaFuncSetAttribute(conv_kernel, cudaFuncAttributeMaxDynamicSharedMemorySize,
                         SMEM_BYTES);

    // 1) Build Gabor bank + reset work queue
    bank_kernel<<<256, 256>>>(kV, sV);

    // 2) Persistent sliding Gabor power transform
    conv_kernel<<<NBLOCKS, NTHREADS, SMEM_BYTES>>>(x, out);
}

// round 4
// speedup vs baseline: 2.9284x; 2.4811x over previous
#include <cuda_runtime.h>
#include <cuda_bf16.h>
#include <math.h>
#include <stdint.h>

// Problem constants
#define BB 16
#define CC 8
#define LL 16384
#define RR 32

#define TM 512                 // t rows per CTA tile
#define NTILES 4096            // c-major: c=g>>9, b=(g>>5)&15, seg=g&31
#define NBLOCKS 152
#define NTHREADS 256           // 8 warps, each warp: m64 x n64

#define BSTRIDE 132            // uint32 words per B row (264 bf16, padded +4B)

// SMEM offsets (bytes)
#define BH_OFF 0                         // B_hi: 64 rows * 132 words = 33792 B
#define BL_OFF 33792                     // B_lo
#define XW_OFF 67584                     // fp32 window: 776 floats (3104 B)
#define PEH_OFF (XW_OFF + 3104)          // even-pair hi: 384 words (+16 pad)
#define POH_OFF (PEH_OFF + 1600)         // odd-pair hi   (400-word spacing: +16 banks)
#define PEL_OFF (POH_OFF + 1600)
#define POL_OFF (PEL_OFF + 1600)
#define SG_OFF  (POL_OFF + 1600)
#define SMEM_BYTES (SG_OFF + 16)

// Precomputed Gabor bank, bf16 hi/lo, padded B layout: row n (0..63), tap w:
//   g_bh[c][n*264 + w]
__device__ __align__(16) __nv_bfloat16 g_bh[CC][64 * 2 * BSTRIDE];
__device__ __align__(16) __nv_bfloat16 g_bl[CC][64 * 2 * BSTRIDE];
__device__ unsigned int g_counter;

__global__ void bank_kernel(const float* __restrict__ kV, const float* __restrict__ sV) {
    int idx = blockIdx.x * blockDim.x + threadIdx.x;
    if (idx == 0) g_counter = 0;
    if (idx >= 65536) return;
    int f = idx >> 8, w = idx & 255;
    float k = kV[f], s = sV[f];
    float phase = ((float)(-2.0 * M_PI / 256.0) * k) * (float)w;
    double sp, cp;
    sincos((double)phase, &sp, &cp);
    float nm = (float)w - 128.0f;
    float s2 = s * s;
    float inv2s2 = 1.0f / (2.0f * s2);
    float coef = 1.0f / sqrtf(2.0f * (float)M_PI * s2);
    float gauss = coef * expf(-inv2s2 * nm * nm);
    float fre = (float)cp * gauss, fim = (float)sp * gauss;
    int c = f >> 5, r = 31 - (f & 31);        // output-order r (reversed)
    // n = 2r -> real, n = 2r+1 -> imag
    __nv_bfloat16 h = __float2bfloat16(fre);
    __nv_bfloat16 l = __float2bfloat16(fre - __bfloat162float(h));
    g_bh[c][(2 * r) * 264 + w] = h;
    g_bl[c][(2 * r) * 264 + w] = l;
    h = __float2bfloat16(fim);
    l = __float2bfloat16(fim - __bfloat162float(h));
    g_bh[c][(2 * r + 1) * 264 + w] = h;
    g_bl[c][(2 * r + 1) * 264 + w] = l;
}

__device__ __forceinline__ uint32_t pack2(__nv_bfloat16 a, __nv_bfloat16 b) {
    __nv_bfloat162 t(a, b);   // .x = a = low half = smaller k
    return *reinterpret_cast<uint32_t*>(&t);
}

__device__ __forceinline__ void mma16816(float* d,
                                         uint32_t a0, uint32_t a1, uint32_t a2, uint32_t a3,
                                         uint32_t b0, uint32_t b1) {
    asm volatile(
        "mma.sync.aligned.m16n8k16.row.col.f32.bf16.bf16.f32 "
        "{%0,%1,%2,%3}, {%4,%5,%6,%7}, {%8,%9}, {%0,%1,%2,%3};"
        : "+f"(d[0]), "+f"(d[1]), "+f"(d[2]), "+f"(d[3])
        : "r"(a0), "r"(a1), "r"(a2), "r"(a3), "r"(b0), "r"(b1));
}

__global__ void __launch_bounds__(NTHREADS, 1)
conv_kernel(const float* __restrict__ x, float* __restrict__ out) {
    extern __shared__ unsigned char smem[];
    float* xw = (float*)(smem + XW_OFF);
    uint32_t* PEHw = (uint32_t*)(smem + PEH_OFF);
    uint32_t* POHw = (uint32_t*)(smem + POH_OFF);
    uint32_t* PELw = (uint32_t*)(smem + PEL_OFF);
    uint32_t* POLw = (uint32_t*)(smem + POL_OFF);
    const uint32_t* BHw = (const uint32_t*)(smem + BH_OFF);
    const uint32_t* BLw = (const uint32_t*)(smem + BL_OFF);
    unsigned int* sgp = (unsigned int*)(smem + SG_OFF);

    int tid  = threadIdx.x;
    int wid  = tid >> 5;
    int lane = tid & 31;
    int lq   = lane >> 2;     // 0..7
    int lr   = lane & 3;      // 0..3
    int mwarp = wid * 64;
    int odd = lq & 1;
    int abase = (mwarp >> 1) + (lq >> 1) + lr;

    if (tid == 0) sgp[0] = atomicAdd(&g_counter, 1u);
    __syncthreads();
    unsigned int g = sgp[0];

    // prefetch first tile's x window: xw[j] = x[b, t0-128+j, c], j in [0,769)
    float v0 = 0, v1 = 0, v2 = 0, v3 = 0;
    {
        unsigned int gc = (g < NTILES) ? g : 0u;
        int c2 = gc >> 9, b2 = (gc >> 5) & 15, t02 = (int)(gc & 31) << 9;
        const float* xb = x + (size_t)b2 * LL * CC + c2;
        int l = t02 - 128 + tid;
        v0 = (l >= 0 && l < LL) ? xb[(size_t)l * CC] : 0.0f;
        v1 = (l + 256 < LL) ? xb[(size_t)(l + 256) * CC] : 0.0f;
        v2 = (l + 512 < LL) ? xb[(size_t)(l + 512) * CC] : 0.0f;
        if (tid == 0) { int l3 = t02 + 640; v3 = (l3 < LL) ? xb[(size_t)l3 * CC] : 0.0f; }
    }

    int cur_c = -1;
    while (g < NTILES) {
        int c = g >> 9, b = (g >> 5) & 15, t0 = (int)(g & 31) << 9;

        __syncthreads();   // B1: previous tile's smem readers are done

        if (c != cur_c) {  // stage B_hi/B_lo (flat 33792B x2 copy)
            const uint4* sH = (const uint4*)g_bh[c];
            const uint4* sL = (const uint4*)g_bl[c];
            uint4* dH = (uint4*)(smem + BH_OFF);
            uint4* dL = (uint4*)(smem + BL_OFF);
            for (int i = tid; i < 2112; i += NTHREADS) { dH[i] = sH[i]; dL[i] = sL[i]; }
            cur_c = c;
        }

        // stage fp32 window
        xw[tid] = v0; xw[tid + 256] = v1; xw[tid + 512] = v2;
        if (tid == 0) xw[768] = v3;
        if (tid == 0) sgp[1] = atomicAdd(&g_counter, 1u);
        __syncthreads();   // mid-barrier: xw visible

        // build hi/lo even/odd bf16-pair arrays (384 entries)
        {
            int i = tid;
            {
                float a0 = xw[2 * i], a1 = xw[2 * i + 1], a2 = xw[2 * i + 2];
                __nv_bfloat16 h0 = __float2bfloat16(a0);
                __nv_bfloat16 l0 = __float2bfloat16(a0 - __bfloat162float(h0));
                __nv_bfloat16 h1 = __float2bfloat16(a1);
                __nv_bfloat16 l1 = __float2bfloat16(a1 - __bfloat162float(h1));
                __nv_bfloat16 h2 = __float2bfloat16(a2);
                __nv_bfloat16 l2 = __float2bfloat16(a2 - __bfloat162float(h2));
                PEHw[i] = pack2(h0, h1); POHw[i] = pack2(h1, h2);
                PELw[i] = pack2(l0, l1); POLw[i] = pack2(l1, l2);
            }
            if (tid < 128) {
                i = tid + 256;
                float a0 = xw[2 * i], a1 = xw[2 * i + 1], a2 = xw[2 * i + 2];
                __nv_bfloat16 h0 = __float2bfloat16(a0);
                __nv_bfloat16 l0 = __float2bfloat16(a0 - __bfloat162float(h0));
                __nv_bfloat16 h1 = __float2bfloat16(a1);
                __nv_bfloat16 l1 = __float2bfloat16(a1 - __bfloat162float(h1));
                __nv_bfloat16 h2 = __float2bfloat16(a2);
                __nv_bfloat16 l2 = __float2bfloat16(a2 - __bfloat162float(h2));
                PEHw[i] = pack2(h0, h1); POHw[i] = pack2(h1, h2);
                PELw[i] = pack2(l0, l1); POLw[i] = pack2(l1, l2);
            }
        }
        __syncthreads();   // B2: pairs + B + next-tile id visible
        unsigned int gn = sgp[1];

        // prefetch next tile's x (LDG latency hides under ~12K cyc of MMA)
        {
            unsigned int gc = (gn < NTILES) ? gn : 0u;
            int c2 = gc >> 9, b2 = (gc >> 5) & 15, t02 = (int)(gc & 31) << 9;
            const float* xb = x + (size_t)b2 * LL * CC + c2;
            int l = t02 - 128 + tid;
            v0 = (l >= 0 && l < LL) ? xb[(size_t)l * CC] : 0.0f;
            v1 = (l + 256 < LL) ? xb[(size_t)(l + 256) * CC] : 0.0f;
            v2 = (l + 512 < LL) ? xb[(size_t)(l + 512) * CC] : 0.0f;
            if (tid == 0) { int l3 = t02 + 640; v3 = (l3 < LL) ? xb[(size_t)l3 * CC] : 0.0f; }
        }

        // ---- 3-pass hi/lo bf16 GEMM: D[m64][n64] per warp ----
        float d[128];
#pragma unroll
        for (int i = 0; i < 128; i++) d[i] = 0.0f;

#pragma unroll 1
        for (int pass = 0; pass < 3; pass++) {
            const uint32_t* ap = (pass == 2) ? (odd ? POLw : PELw)
                                             : (odd ? POHw : PEHw);
            const uint32_t* bl = ((pass == 1) ? BLw : BHw) + lq * BSTRIDE + lr;
#pragma unroll 4
            for (int kc = 0; kc < 16; kc++) {
                // A pair words: Hankel sharing -> 9 loads cover 4 m-subtiles
                uint32_t w[9];
#pragma unroll
                for (int u = 0; u < 9; u++) w[u] = ap[abase + kc * 8 + 4 * u];
                // B frags for 8 n-subtiles
                uint32_t bq[16];
#pragma unroll
                for (int ns = 0; ns < 8; ns++) {
                    bq[2 * ns]     = bl[ns * 8 * BSTRIDE + kc * 8];
                    bq[2 * ns + 1] = bl[ns * 8 * BSTRIDE + kc * 8 + 4];
                }
#pragma unroll
                for (int ms = 0; ms < 4; ms++) {
#pragma unroll
                    for (int ns = 0; ns < 8; ns++) {
                        mma16816(d + (ms * 8 + ns) * 4,
                                 w[2 * ms], w[2 * ms + 1], w[2 * ms + 1], w[2 * ms + 2],
                                 bq[2 * ns], bq[2 * ns + 1]);
                    }
                }
            }
        }

        // ---- epilogue: power + store ----
        // D frag (ms,ns): c0,c1 = (cr,ci) @ t = t0+mwarp+ms*16+lq, r = ns*4+lr
        //                 c2,c3 = same @ t+8
        size_t ob = ((size_t)(b * LL + t0 + mwarp + lq)) * (CC * RR) + (size_t)c * RR + lr;
#pragma unroll
        for (int ms = 0; ms < 4; ms++) {
#pragma unroll
            for (int ns = 0; ns < 8; ns++) {
                const float* dd = d + (ms * 8 + ns) * 4;
                float p0 = dd[0] * dd[0] + dd[1] * dd[1];
                float p1 = dd[2] * dd[2] + dd[3] * dd[3];
                out[ob + (size_t)(ms * 16) * (CC * RR) + ns * 4] = p0;
                out[ob + (size_t)(ms * 16 + 8) * (CC * RR) + ns * 4] = p1;
            }
        }

        g = gn;
    }
}

extern "C" void kernel_launch(void* const* d_in, const int* in_sizes, int n_in,
                              void* d_out, int out_size) {
    const float* x  = (const float*)d_in[0];
    const float* kV = (const float*)d_in[1];
    const float* sV = (const float*)d_in[2];
    float* out = (float*)d_out;

    cudaFuncSetAttribute(conv_kernel, cudaFuncAttributeMaxDynamicSharedMemorySize,
                         SMEM_BYTES);

    // 1) Gabor bank (bf16 hi/lo, padded) + work-queue reset
    bank_kernel<<<256, 256>>>(kV, sV);

    // 2) persistent implicit-GEMM wavelet transform (mma.sync bf16)
    conv_kernel<<<NBLOCKS, NTHREADS, SMEM_BYTES>>>(x, out);
}